// round 16
// baseline (speedup 1.0000x reference)
#include <cuda_runtime.h>
#include <cuda_bf16.h>
#include <math.h>
#include <stdint.h>

#define Dm 1024
#define Hh 16
#define HDm 64
#define FFm 4096
#define BATCHm 8
#define SEQm 1024
#define TOKm (BATCHm*SEQm)   /* 8192 */
#define BHm (BATCHm*Hh)      /* 128  */

static __device__ __nv_bfloat16 g_hb [(size_t)TOKm*Dm];
static __device__ __nv_bfloat16 g_qb [(size_t)BHm*SEQm*HDm];
static __device__ __nv_bfloat16 g_kb [(size_t)BHm*SEQm*HDm];
static __device__ __nv_bfloat16 g_vtb[(size_t)BHm*SEQm*HDm];   // [bh, hd, t]
static __device__ __nv_bfloat16 g_ob [(size_t)TOKm*Dm];
static __device__ __nv_bfloat16 g_gb [(size_t)TOKm*FFm];
static __device__ float         g_x1 [(size_t)TOKm*Dm];
static __device__ __nv_bfloat16 w_qkv[(size_t)3*Dm*Dm];
static __device__ __nv_bfloat16 w_proj[(size_t)Dm*Dm];
static __device__ __nv_bfloat16 w_fc1[(size_t)FFm*Dm];
static __device__ __nv_bfloat16 w_fc2[(size_t)Dm*FFm];

// ---------------------------------------------------------------------------
// helpers
// ---------------------------------------------------------------------------
__device__ __forceinline__ void cp16(uint32_t dst, const void* src) {
    asm volatile("cp.async.cg.shared.global [%0], [%1], 16;" :: "r"(dst), "l"(src));
}
__device__ __forceinline__ void mma_bf16(float* c, const uint32_t* a, const uint32_t* b) {
    asm volatile(
        "mma.sync.aligned.m16n8k16.row.col.f32.bf16.bf16.f32 "
        "{%0,%1,%2,%3},{%4,%5,%6,%7},{%8,%9},{%0,%1,%2,%3};"
        : "+f"(c[0]), "+f"(c[1]), "+f"(c[2]), "+f"(c[3])
        : "r"(a[0]), "r"(a[1]), "r"(a[2]), "r"(a[3]), "r"(b[0]), "r"(b[1]));
}
__device__ __forceinline__ void ldsm4(uint32_t* r, uint32_t addr) {
    asm volatile("ldmatrix.sync.aligned.m8n8.x4.shared.b16 {%0,%1,%2,%3}, [%4];"
                 : "=r"(r[0]), "=r"(r[1]), "=r"(r[2]), "=r"(r[3]) : "r"(addr));
}
__device__ __forceinline__ uint32_t packbf(float lo, float hi) {
    uint32_t r;
    asm("cvt.rn.bf16x2.f32 %0, %1, %2;" : "=r"(r) : "f"(hi), "f"(lo));
    return r;
}

// ---------------------------------------------------------------------------
// fp32 -> bf16 conversion, all four weight tensors in one launch
// ---------------------------------------------------------------------------
#define N_QKV (3*Dm*Dm)
#define N_PRJ (Dm*Dm)
#define N_FC1 (FFm*Dm)
#define N_FC2 (Dm*FFm)
__global__ void cvt4_kernel(const float* __restrict__ s0, const float* __restrict__ s1,
                            const float* __restrict__ s2, const float* __restrict__ s3,
                            __nv_bfloat16* __restrict__ d0, __nv_bfloat16* __restrict__ d1,
                            __nv_bfloat16* __restrict__ d2, __nv_bfloat16* __restrict__ d3)
{
    int i = blockIdx.x * 256 + threadIdx.x;
    if (i < N_QKV)                       d0[i] = __float2bfloat16_rn(s0[i]);
    else if (i < N_QKV + N_PRJ)          d1[i - N_QKV] = __float2bfloat16_rn(s1[i - N_QKV]);
    else if (i < N_QKV + N_PRJ + N_FC1)  d2[i - N_QKV - N_PRJ] =
                                             __float2bfloat16_rn(s2[i - N_QKV - N_PRJ]);
    else                                 d3[i - N_QKV - N_PRJ - N_FC1] =
                                             __float2bfloat16_rn(s3[i - N_QKV - N_PRJ - N_FC1]);
}

// ---------------------------------------------------------------------------
// LayerNorm: fp32 in, bf16 out. One block per row (D=1024).
// ---------------------------------------------------------------------------
__global__ void ln_kernel(const float* __restrict__ x,
                          const float* __restrict__ gam,
                          const float* __restrict__ bet,
                          __nv_bfloat16* __restrict__ out)
{
    const float* xr = x + (size_t)blockIdx.x * Dm;
    __nv_bfloat16* orow = out + (size_t)blockIdx.x * Dm;
    int tid = threadIdx.x;

    float s = 0.f, s2 = 0.f;
    for (int i = tid; i < Dm; i += 256) {
        float v = xr[i];
        s += v; s2 += v * v;
    }
    __shared__ float rs[8], rs2[8];
    #pragma unroll
    for (int o = 16; o > 0; o >>= 1) {
        s  += __shfl_xor_sync(0xffffffffu, s,  o);
        s2 += __shfl_xor_sync(0xffffffffu, s2, o);
    }
    if ((tid & 31) == 0) { rs[tid >> 5] = s; rs2[tid >> 5] = s2; }
    __syncthreads();
    if (tid < 32) {
        float a = (tid < 8) ? rs[tid]  : 0.f;
        float b = (tid < 8) ? rs2[tid] : 0.f;
        #pragma unroll
        for (int o = 4; o > 0; o >>= 1) {
            a += __shfl_xor_sync(0xffffffffu, a, o);
            b += __shfl_xor_sync(0xffffffffu, b, o);
        }
        if (tid == 0) { rs[0] = a; rs2[0] = b; }
    }
    __syncthreads();
    float mu  = rs[0] * (1.0f / Dm);
    float var = rs2[0] * (1.0f / Dm) - mu * mu;
    float inv = rsqrtf(var + 1e-5f);
    for (int i = tid; i < Dm; i += 256)
        orow[i] = __float2bfloat16_rn((xr[i] - mu) * inv * gam[i] + bet[i]);
}

// ---------------------------------------------------------------------------
// bf16 tensor-core GEMM. C = A[M,K] @ B^T (both bf16 row-major K-major).
// BM=BN=128, BK=32, 3-stage ring (48KB); 4 warps of 64x64 (MI=4, NI=8):
// 8 LDSM.x4 per 32 HMMA (ratio 4.0, was 2.67). 128 threads/CTA.
// EPI: 2 fp32 bias+residual, 3 bf16 bias+gelu, 5 qkv scatter.
// ---------------------------------------------------------------------------
template<int EPI>
__global__ __launch_bounds__(128)
void tgemm(const __nv_bfloat16* __restrict__ A, const __nv_bfloat16* __restrict__ B,
           float* __restrict__ C, int M, int N, int K,
           const float* __restrict__ bias, const float* __restrict__ res)
{
    constexpr int BM = 128, BN = 128, BK = 32;
    constexpr int MI = 4, NI = 8;
    constexpr int STAGES = 3;
    constexpr int TILE32 = BM * 16;

    __shared__ alignas(1024) uint32_t As32[STAGES * TILE32];
    __shared__ alignas(1024) uint32_t Bs32[STAGES * TILE32];

    int tid = threadIdx.x, lane = tid & 31, warp = tid >> 5;
    int g = lane >> 2, tg = lane & 3;
    int wm = (warp & 1) * 64, wn = (warp >> 1) * 64;
    int m0 = blockIdx.y * BM, n0 = blockIdx.x * BN;

    uint32_t sA = (uint32_t)__cvta_generic_to_shared(&As32[0]);
    uint32_t sB = (uint32_t)__cvta_generic_to_shared(&Bs32[0]);

    auto stage = [&](int st, int k0) {
        #pragma unroll
        for (int i = tid; i < 512; i += 128) {
            int r = i >> 2, c = i & 3;
            cp16(sA + (uint32_t)((st * TILE32 + r * 16 + ((c ^ ((r >> 1) & 3)) << 2)) * 4),
                 A + (size_t)(m0 + r) * K + k0 + c * 8);
        }
        #pragma unroll
        for (int i = tid; i < 512; i += 128) {
            int r = i >> 2, c = i & 3;
            cp16(sB + (uint32_t)((st * TILE32 + r * 16 + ((c ^ ((r >> 1) & 3)) << 2)) * 4),
                 B + (size_t)(n0 + r) * K + k0 + c * 8);
        }
        asm volatile("cp.async.commit_group;");
    };

    float acc[MI][NI][4] = {};

    int lr = lane & 15, lh = lane >> 4;
    uint32_t aoff[MI], boff[4];
    int sa[MI], sbw[4];
    #pragma unroll
    for (int mi = 0; mi < MI; mi++) {
        int r = wm + mi * 16 + lr;
        aoff[mi] = (uint32_t)(r * 64);
        sa[mi] = (r >> 1) & 3;
    }
    #pragma unroll
    for (int p = 0; p < 4; p++) {
        int r = wn + p * 16 + lr;
        boff[p] = (uint32_t)(r * 64);
        sbw[p] = (r >> 1) & 3;
    }

    int NKT = K / BK;
    stage(0, 0);
    stage(1, BK);
    for (int kt = 0; kt < NKT; kt++) {
        int cur = kt % STAGES;
        if (kt + 2 < NKT) stage((kt + 2) % STAGES, (kt + 2) * BK);
        else              asm volatile("cp.async.commit_group;");
        asm volatile("cp.async.wait_group 2;");
        __syncthreads();

        uint32_t AcA = sA + (uint32_t)(cur * TILE32 * 4);
        uint32_t AcB = sB + (uint32_t)(cur * TILE32 * 4);
        #pragma unroll
        for (int kk = 0; kk < 2; kk++) {
            int ch = kk * 2 + lh;
            uint32_t af[MI][4];
            uint32_t bfv[NI][2];
            #pragma unroll
            for (int mi = 0; mi < MI; mi++)
                ldsm4(af[mi], AcA + aoff[mi] + (uint32_t)(((ch ^ sa[mi]) << 4)));
            #pragma unroll
            for (int p = 0; p < 4; p++) {
                uint32_t r4[4];
                ldsm4(r4, AcB + boff[p] + (uint32_t)(((ch ^ sbw[p]) << 4)));
                bfv[2 * p    ][0] = r4[0];
                bfv[2 * p + 1][0] = r4[1];
                bfv[2 * p    ][1] = r4[2];
                bfv[2 * p + 1][1] = r4[3];
            }
            #pragma unroll
            for (int mi = 0; mi < MI; mi++)
                #pragma unroll
                for (int ni = 0; ni < NI; ni++)
                    mma_bf16(acc[mi][ni], af[mi], bfv[ni]);
        }
        __syncthreads();
    }

    // ---- epilogue ----
    #pragma unroll
    for (int mi = 0; mi < MI; mi++) {
        #pragma unroll
        for (int ni = 0; ni < NI; ni++) {
            #pragma unroll
            for (int half = 0; half < 2; half++) {
                int m = m0 + wm + mi * 16 + g + half * 8;
                float v0 = acc[mi][ni][half * 2 + 0];
                float v1 = acc[mi][ni][half * 2 + 1];
                int n = n0 + wn + ni * 8 + tg * 2;
                if (EPI == 2) {
                    float2 w;
                    w.x = v0 + bias[n    ] + res[(size_t)m * N + n    ];
                    w.y = v1 + bias[n + 1] + res[(size_t)m * N + n + 1];
                    *(float2*)&C[(size_t)m * N + n] = w;
                } else if (EPI == 3) {
                    float t0 = v0 + bias[n], t1 = v1 + bias[n + 1];
                    t0 = 0.5f * t0 * (1.f + erff(t0 * 0.70710678118654752f));
                    t1 = 0.5f * t1 * (1.f + erff(t1 * 0.70710678118654752f));
                    ((uint32_t*)C)[((size_t)m * N + n) >> 1] = packbf(t0, t1);
                } else if (EPI == 5) {
                    #pragma unroll
                    for (int e = 0; e < 2; e++) {
                        float v = e ? v1 : v0;
                        int nn = n + e;
                        int which = nn >> 10;
                        int r = nn & 1023;
                        int hh = r >> 6, hd = r & 63;
                        int bb = m >> 10, t = m & 1023;
                        int bh = bb * Hh + hh;
                        if (which == 0)
                            g_qb[((size_t)bh * SEQm + t) * HDm + hd] =
                                __float2bfloat16_rn((v + bias[r]) * 0.125f);
                        else if (which == 1)
                            g_kb[((size_t)bh * SEQm + t) * HDm + hd] =
                                __float2bfloat16_rn(v);
                        else
                            g_vtb[((size_t)bh * HDm + hd) * SEQm + t] =
                                __float2bfloat16_rn(v + res[r]);
                    }
                }
            }
        }
    }
}

// ---------------------------------------------------------------------------
// Fused attention (no-max softmax) — unchanged from R15.
// ---------------------------------------------------------------------------
__global__ __launch_bounds__(256, 2)
void flash(const __nv_bfloat16* __restrict__ Q, const __nv_bfloat16* __restrict__ K,
           const __nv_bfloat16* __restrict__ Vt, __nv_bfloat16* __restrict__ O)
{
    __shared__ alignas(1024) uint32_t Qs[4096];
    __shared__ alignas(1024) uint32_t Ks[2][2048];
    __shared__ alignas(1024) uint32_t Vs[2][2048];

    int tid = threadIdx.x, lane = tid & 31, warp = tid >> 5;
    int g = lane >> 2, tg = lane & 3;
    int lr = lane & 15, lh = lane >> 4;
    int wm = warp * 16;
    int q0 = blockIdx.x * 128;
    long z = blockIdx.y;
    const __nv_bfloat16* Qb = Q + (z * SEQm + q0) * HDm;
    const __nv_bfloat16* Kb = K + z * (long)SEQm * HDm;
    const __nv_bfloat16* Vb = Vt + z * (long)SEQm * HDm;

    uint32_t sQ = (uint32_t)__cvta_generic_to_shared(&Qs[0]);
    uint32_t sK = (uint32_t)__cvta_generic_to_shared(&Ks[0][0]);
    uint32_t sV = (uint32_t)__cvta_generic_to_shared(&Vs[0][0]);

    #pragma unroll
    for (int i = tid; i < 1024; i += 256) {
        int seg = i >> 9, r = (i >> 2) & 127, c = i & 3;
        cp16(sQ + (uint32_t)((seg * 2048 + r * 16 + ((c ^ ((r >> 1) & 3)) << 2)) * 4),
             Qb + r * HDm + seg * 32 + c * 8);
    }
    asm volatile("cp.async.commit_group;");

    auto stageKV = [&](int st, int t0) {
        #pragma unroll
        for (int i = tid; i < 512; i += 256) {
            int seg = i >> 8, r = (i >> 2) & 63, c = i & 3;
            uint32_t off = (uint32_t)((st * 2048 + seg * 1024 + r * 16 +
                                       ((c ^ ((r >> 1) & 3)) << 2)) * 4);
            cp16(sK + off, Kb + (size_t)(t0 + r) * HDm + seg * 32 + c * 8);
        }
        #pragma unroll
        for (int i = tid; i < 512; i += 256) {
            int seg = i >> 8, r = (i >> 2) & 63, c = i & 3;
            uint32_t off = (uint32_t)((st * 2048 + seg * 1024 + r * 16 +
                                       ((c ^ ((r >> 1) & 3)) << 2)) * 4);
            cp16(sV + off, Vb + (size_t)r * SEQm + t0 + seg * 32 + c * 8);
        }
        asm volatile("cp.async.commit_group;");
    };

    stageKV(0, 0);
    asm volatile("cp.async.wait_group 0;");
    __syncthreads();

    uint32_t aq[4][4];
    {
        int rq = wm + lr;
        int swq = (rq >> 1) & 3;
        #pragma unroll
        for (int ch = 0; ch < 4; ch++) {
            int seg = ch >> 1, c16 = (ch & 1) * 2 + lh;
            ldsm4(aq[ch], sQ + (uint32_t)((seg * 2048 + rq * 16 +
                                           ((c16 ^ swq) << 2)) * 4));
        }
    }

    float accO[8][4] = {};
    float rs0 = 0.f, rs1 = 0.f;

    for (int jt = 0; jt < 16; jt++) {
        if (jt + 1 < 16) stageKV((jt + 1) & 1, (jt + 1) * 64);
        else             asm volatile("cp.async.commit_group;");
        asm volatile("cp.async.wait_group 1;");
        __syncthreads();

        uint32_t bK = sK + (uint32_t)((jt & 1) * 2048 * 4);
        uint32_t bV = sV + (uint32_t)((jt & 1) * 2048 * 4);

        float accS[8][4] = {};
        #pragma unroll
        for (int ch = 0; ch < 4; ch++) {
            int seg = ch >> 1, c16 = (ch & 1) * 2 + lh;
            uint32_t bfv[8][2];
            #pragma unroll
            for (int p = 0; p < 4; p++) {
                int rb = p * 16 + lr;
                uint32_t r4[4];
                ldsm4(r4, bK + (uint32_t)((seg * 1024 + rb * 16 +
                                           ((c16 ^ ((rb >> 1) & 3)) << 2)) * 4));
                bfv[2 * p    ][0] = r4[0];
                bfv[2 * p + 1][0] = r4[1];
                bfv[2 * p    ][1] = r4[2];
                bfv[2 * p + 1][1] = r4[3];
            }
            #pragma unroll
            for (int ni = 0; ni < 8; ni++)
                mma_bf16(accS[ni], aq[ch], bfv[ni]);
        }

        uint32_t ap[4][4];
        #pragma unroll
        for (int t = 0; t < 4; t++) {
            ap[t][0] = packbf(__expf(accS[2*t    ][0]), __expf(accS[2*t    ][1]));
            ap[t][1] = packbf(__expf(accS[2*t    ][2]), __expf(accS[2*t    ][3]));
            ap[t][2] = packbf(__expf(accS[2*t + 1][0]), __expf(accS[2*t + 1][1]));
            ap[t][3] = packbf(__expf(accS[2*t + 1][2]), __expf(accS[2*t + 1][3]));
            float2 f0 = __bfloat1622float2(*(__nv_bfloat162*)&ap[t][0]);
            float2 f2 = __bfloat1622float2(*(__nv_bfloat162*)&ap[t][2]);
            rs0 += (f0.x + f0.y) + (f2.x + f2.y);
            float2 f1 = __bfloat1622float2(*(__nv_bfloat162*)&ap[t][1]);
            float2 f3 = __bfloat1622float2(*(__nv_bfloat162*)&ap[t][3]);
            rs1 += (f1.x + f1.y) + (f3.x + f3.y);
        }

        #pragma unroll
        for (int ch = 0; ch < 4; ch++) {
            int seg = ch >> 1, c16 = (ch & 1) * 2 + lh;
            uint32_t bfv[8][2];
            #pragma unroll
            for (int p = 0; p < 4; p++) {
                int rb = p * 16 + lr;
                uint32_t r4[4];
                ldsm4(r4, bV + (uint32_t)((seg * 1024 + rb * 16 +
                                           ((c16 ^ ((rb >> 1) & 3)) << 2)) * 4));
                bfv[2 * p    ][0] = r4[0];
                bfv[2 * p + 1][0] = r4[1];
                bfv[2 * p    ][1] = r4[2];
                bfv[2 * p + 1][1] = r4[3];
            }
            #pragma unroll
            for (int ni = 0; ni < 8; ni++)
                mma_bf16(accO[ni], ap[ch], bfv[ni]);
        }
        __syncthreads();
    }

    rs0 += __shfl_xor_sync(0xffffffffu, rs0, 1);
    rs0 += __shfl_xor_sync(0xffffffffu, rs0, 2);
    rs1 += __shfl_xor_sync(0xffffffffu, rs1, 1);
    rs1 += __shfl_xor_sync(0xffffffffu, rs1, 2);
    float inv0 = 1.f / rs0, inv1 = 1.f / rs1;

    int bb = (int)(z >> 4), hh = (int)(z & 15);
    uint32_t* O32 = (uint32_t*)O;
    size_t base0 = ((size_t)bb * SEQm + q0 + wm + g) * Dm + hh * HDm;
    size_t base1 = base0 + (size_t)8 * Dm;
    #pragma unroll
    for (int ni = 0; ni < 8; ni++) {
        int c = ni * 8 + tg * 2;
        O32[(base0 + c) >> 1] = packbf(accO[ni][0] * inv0, accO[ni][1] * inv0);
        O32[(base1 + c) >> 1] = packbf(accO[ni][2] * inv1, accO[ni][3] * inv1);
    }
}

// ---------------------------------------------------------------------------
extern "C" void kernel_launch(void* const* d_in, const int* in_sizes, int n_in,
                              void* d_out, int out_size)
{
    const float* x      = (const float*)d_in[0];
    const float* ln1_g  = (const float*)d_in[1];
    const float* ln1_b  = (const float*)d_in[2];
    const float* ln2_g  = (const float*)d_in[3];
    const float* ln2_b  = (const float*)d_in[4];
    const float* qkv_w  = (const float*)d_in[5];
    const float* q_bias = (const float*)d_in[6];
    const float* v_bias = (const float*)d_in[7];
    const float* proj_w = (const float*)d_in[8];
    const float* proj_b = (const float*)d_in[9];
    const float* fc1_w  = (const float*)d_in[10];
    const float* fc1_b  = (const float*)d_in[11];
    const float* fc2_w  = (const float*)d_in[12];
    const float* fc2_b  = (const float*)d_in[13];
    float* out = (float*)d_out;

    __nv_bfloat16 *hb, *qb, *kb, *vtb, *ob, *gb, *wq, *wp, *w1, *w2;
    float *x1;
    cudaGetSymbolAddress((void**)&hb,  g_hb);
    cudaGetSymbolAddress((void**)&qb,  g_qb);
    cudaGetSymbolAddress((void**)&kb,  g_kb);
    cudaGetSymbolAddress((void**)&vtb, g_vtb);
    cudaGetSymbolAddress((void**)&ob,  g_ob);
    cudaGetSymbolAddress((void**)&gb,  g_gb);
    cudaGetSymbolAddress((void**)&x1,  g_x1);
    cudaGetSymbolAddress((void**)&wq,  w_qkv);
    cudaGetSymbolAddress((void**)&wp,  w_proj);
    cudaGetSymbolAddress((void**)&w1,  w_fc1);
    cudaGetSymbolAddress((void**)&w2,  w_fc2);

    // 0. weight conversion to bf16 (single launch)
    {
        int total = N_QKV + N_PRJ + N_FC1 + N_FC2;
        cvt4_kernel<<<(total + 255) / 256, 256>>>(qkv_w, proj_w, fc1_w, fc2_w,
                                                  wq, wp, w1, w2);
    }

    // 1. LN1 -> bf16
    ln_kernel<<<TOKm, 256>>>(x, ln1_g, ln1_b, hb);

    // 2. QKV = h @ qkv_w^T, fused scatter (q scaled+biased, k, v^T biased)
    tgemm<5><<<dim3(3072/128, TOKm/128), 128>>>(
        hb, wq, nullptr, TOKm, 3*Dm, Dm, q_bias, v_bias);

    // 3. fused attention: o = softmax(q k^T) v -> bf16 [b,t,(h,hd)]
    flash<<<dim3(SEQm/128, BHm), 256>>>(qb, kb, vtb, ob);

    // 4. x1 = x + o @ proj_w^T + proj_b  (fp32)
    tgemm<2><<<dim3(Dm/128, TOKm/128), 128>>>(
        ob, wp, x1, TOKm, Dm, Dm, proj_b, x);

    // 5. LN2 -> bf16
    ln_kernel<<<TOKm, 256>>>(x1, ln2_g, ln2_b, hb);

    // 6. g = gelu(h @ fc1_w^T + fc1_b) -> bf16
    tgemm<3><<<dim3(FFm/128, TOKm/128), 128>>>(
        hb, w1, (float*)gb, TOKm, FFm, Dm, fc1_b, nullptr);

    // 7. out = x1 + g @ fc2_w^T + fc2_b  (fp32)
    tgemm<2><<<dim3(Dm/128, TOKm/128), 128>>>(
        gb, w2, out, TOKm, Dm, FFm, fc2_b, x1);
}

// round 17
// speedup vs baseline: 1.0754x; 1.0754x over previous
#include <cuda_runtime.h>
#include <cuda_bf16.h>
#include <math.h>
#include <stdint.h>

#define Dm 1024
#define Hh 16
#define HDm 64
#define FFm 4096
#define BATCHm 8
#define SEQm 1024
#define TOKm (BATCHm*SEQm)   /* 8192 */
#define BHm (BATCHm*Hh)      /* 128  */

static __device__ __nv_bfloat16 g_hb [(size_t)TOKm*Dm];
static __device__ __nv_bfloat16 g_qb [(size_t)BHm*SEQm*HDm];
static __device__ __nv_bfloat16 g_kb [(size_t)BHm*SEQm*HDm];
static __device__ __nv_bfloat16 g_vtb[(size_t)BHm*SEQm*HDm];   // [bh, hd, t]
static __device__ __nv_bfloat16 g_ob [(size_t)TOKm*Dm];
static __device__ __nv_bfloat16 g_gb [(size_t)TOKm*FFm];
static __device__ float         g_x1 [(size_t)TOKm*Dm];
static __device__ __nv_bfloat16 w_qkv[(size_t)3*Dm*Dm];
static __device__ __nv_bfloat16 w_proj[(size_t)Dm*Dm];
static __device__ __nv_bfloat16 w_fc1[(size_t)FFm*Dm];
static __device__ __nv_bfloat16 w_fc2[(size_t)Dm*FFm];

// ---------------------------------------------------------------------------
// helpers
// ---------------------------------------------------------------------------
__device__ __forceinline__ void cp16(uint32_t dst, const void* src) {
    asm volatile("cp.async.cg.shared.global [%0], [%1], 16;" :: "r"(dst), "l"(src));
}
__device__ __forceinline__ void mma_bf16(float* c, const uint32_t* a, const uint32_t* b) {
    asm volatile(
        "mma.sync.aligned.m16n8k16.row.col.f32.bf16.bf16.f32 "
        "{%0,%1,%2,%3},{%4,%5,%6,%7},{%8,%9},{%0,%1,%2,%3};"
        : "+f"(c[0]), "+f"(c[1]), "+f"(c[2]), "+f"(c[3])
        : "r"(a[0]), "r"(a[1]), "r"(a[2]), "r"(a[3]), "r"(b[0]), "r"(b[1]));
}
__device__ __forceinline__ void ldsm4(uint32_t* r, uint32_t addr) {
    asm volatile("ldmatrix.sync.aligned.m8n8.x4.shared.b16 {%0,%1,%2,%3}, [%4];"
                 : "=r"(r[0]), "=r"(r[1]), "=r"(r[2]), "=r"(r[3]) : "r"(addr));
}
__device__ __forceinline__ uint32_t packbf(float lo, float hi) {
    uint32_t r;
    asm("cvt.rn.bf16x2.f32 %0, %1, %2;" : "=r"(r) : "f"(hi), "f"(lo));
    return r;
}

// ---------------------------------------------------------------------------
// fp32 -> bf16 conversion, all four weight tensors in one launch
// ---------------------------------------------------------------------------
#define N_QKV (3*Dm*Dm)
#define N_PRJ (Dm*Dm)
#define N_FC1 (FFm*Dm)
#define N_FC2 (Dm*FFm)
__global__ void cvt4_kernel(const float* __restrict__ s0, const float* __restrict__ s1,
                            const float* __restrict__ s2, const float* __restrict__ s3,
                            __nv_bfloat16* __restrict__ d0, __nv_bfloat16* __restrict__ d1,
                            __nv_bfloat16* __restrict__ d2, __nv_bfloat16* __restrict__ d3)
{
    int i = blockIdx.x * 256 + threadIdx.x;
    if (i < N_QKV)                       d0[i] = __float2bfloat16_rn(s0[i]);
    else if (i < N_QKV + N_PRJ)          d1[i - N_QKV] = __float2bfloat16_rn(s1[i - N_QKV]);
    else if (i < N_QKV + N_PRJ + N_FC1)  d2[i - N_QKV - N_PRJ] =
                                             __float2bfloat16_rn(s2[i - N_QKV - N_PRJ]);
    else                                 d3[i - N_QKV - N_PRJ - N_FC1] =
                                             __float2bfloat16_rn(s3[i - N_QKV - N_PRJ - N_FC1]);
}

// ---------------------------------------------------------------------------
// LayerNorm: fp32 in, bf16 out. One block per row (D=1024).
// ---------------------------------------------------------------------------
__global__ void ln_kernel(const float* __restrict__ x,
                          const float* __restrict__ gam,
                          const float* __restrict__ bet,
                          __nv_bfloat16* __restrict__ out)
{
    const float* xr = x + (size_t)blockIdx.x * Dm;
    __nv_bfloat16* orow = out + (size_t)blockIdx.x * Dm;
    int tid = threadIdx.x;

    float s = 0.f, s2 = 0.f;
    for (int i = tid; i < Dm; i += 256) {
        float v = xr[i];
        s += v; s2 += v * v;
    }
    __shared__ float rs[8], rs2[8];
    #pragma unroll
    for (int o = 16; o > 0; o >>= 1) {
        s  += __shfl_xor_sync(0xffffffffu, s,  o);
        s2 += __shfl_xor_sync(0xffffffffu, s2, o);
    }
    if ((tid & 31) == 0) { rs[tid >> 5] = s; rs2[tid >> 5] = s2; }
    __syncthreads();
    if (tid < 32) {
        float a = (tid < 8) ? rs[tid]  : 0.f;
        float b = (tid < 8) ? rs2[tid] : 0.f;
        #pragma unroll
        for (int o = 4; o > 0; o >>= 1) {
            a += __shfl_xor_sync(0xffffffffu, a, o);
            b += __shfl_xor_sync(0xffffffffu, b, o);
        }
        if (tid == 0) { rs[0] = a; rs2[0] = b; }
    }
    __syncthreads();
    float mu  = rs[0] * (1.0f / Dm);
    float var = rs2[0] * (1.0f / Dm) - mu * mu;
    float inv = rsqrtf(var + 1e-5f);
    for (int i = tid; i < Dm; i += 256)
        orow[i] = __float2bfloat16_rn((xr[i] - mu) * inv * gam[i] + bet[i]);
}

// ---------------------------------------------------------------------------
// bf16 tensor-core GEMM (R15 geometry: 8 warps of 64x32, 256 threads).
// C = A[M,K] @ B^T. BM=BN=128, BK=32, 3-stage ring, XOR swizzle, ldmatrix.
// EPI: 2 fp32 bias+residual, 3 bf16 bias+gelu, 5 qkv scatter.
// ---------------------------------------------------------------------------
template<int EPI>
__global__ __launch_bounds__(256)
void tgemm(const __nv_bfloat16* __restrict__ A, const __nv_bfloat16* __restrict__ B,
           float* __restrict__ C, int M, int N, int K,
           const float* __restrict__ bias, const float* __restrict__ res)
{
    constexpr int BM = 128, BN = 128, BK = 32;
    constexpr int MI = 4, NI = 4;
    constexpr int STAGES = 3;
    constexpr int TILE32 = BM * 16;

    __shared__ alignas(1024) uint32_t As32[STAGES * TILE32];
    __shared__ alignas(1024) uint32_t Bs32[STAGES * TILE32];

    int tid = threadIdx.x, lane = tid & 31, warp = tid >> 5;
    int g = lane >> 2, tg = lane & 3;
    int wm = (warp % 2) * 64, wn = (warp / 2) * 32;
    int m0 = blockIdx.y * BM, n0 = blockIdx.x * BN;

    uint32_t sA = (uint32_t)__cvta_generic_to_shared(&As32[0]);
    uint32_t sB = (uint32_t)__cvta_generic_to_shared(&Bs32[0]);

    auto stage = [&](int st, int k0) {
        #pragma unroll
        for (int i = tid; i < 512; i += 256) {
            int r = i >> 2, c = i & 3;
            cp16(sA + (uint32_t)((st * TILE32 + r * 16 + ((c ^ ((r >> 1) & 3)) << 2)) * 4),
                 A + (size_t)(m0 + r) * K + k0 + c * 8);
        }
        #pragma unroll
        for (int i = tid; i < 512; i += 256) {
            int r = i >> 2, c = i & 3;
            cp16(sB + (uint32_t)((st * TILE32 + r * 16 + ((c ^ ((r >> 1) & 3)) << 2)) * 4),
                 B + (size_t)(n0 + r) * K + k0 + c * 8);
        }
        asm volatile("cp.async.commit_group;");
    };

    float acc[MI][NI][4] = {};

    int lr = lane & 15, lh = lane >> 4;
    uint32_t aoff[MI], boff[2];
    int sa[MI], sbw[2];
    #pragma unroll
    for (int mi = 0; mi < MI; mi++) {
        int r = wm + mi * 16 + lr;
        aoff[mi] = (uint32_t)(r * 64);
        sa[mi] = (r >> 1) & 3;
    }
    #pragma unroll
    for (int p = 0; p < 2; p++) {
        int r = wn + p * 16 + lr;
        boff[p] = (uint32_t)(r * 64);
        sbw[p] = (r >> 1) & 3;
    }

    int NKT = K / BK;
    stage(0, 0);
    stage(1, BK);
    for (int kt = 0; kt < NKT; kt++) {
        int cur = kt % STAGES;
        if (kt + 2 < NKT) stage((kt + 2) % STAGES, (kt + 2) * BK);
        else              asm volatile("cp.async.commit_group;");
        asm volatile("cp.async.wait_group 2;");
        __syncthreads();

        uint32_t AcA = sA + (uint32_t)(cur * TILE32 * 4);
        uint32_t AcB = sB + (uint32_t)(cur * TILE32 * 4);
        #pragma unroll
        for (int kk = 0; kk < 2; kk++) {
            int ch = kk * 2 + lh;
            uint32_t af[MI][4];
            uint32_t bfv[NI][2];
            #pragma unroll
            for (int mi = 0; mi < MI; mi++)
                ldsm4(af[mi], AcA + aoff[mi] + (uint32_t)(((ch ^ sa[mi]) << 4)));
            #pragma unroll
            for (int p = 0; p < 2; p++) {
                uint32_t r4[4];
                ldsm4(r4, AcB + boff[p] + (uint32_t)(((ch ^ sbw[p]) << 4)));
                bfv[2 * p    ][0] = r4[0];
                bfv[2 * p + 1][0] = r4[1];
                bfv[2 * p    ][1] = r4[2];
                bfv[2 * p + 1][1] = r4[3];
            }
            #pragma unroll
            for (int mi = 0; mi < MI; mi++)
                #pragma unroll
                for (int ni = 0; ni < NI; ni++)
                    mma_bf16(acc[mi][ni], af[mi], bfv[ni]);
        }
        __syncthreads();
    }

    // ---- epilogue ----
    #pragma unroll
    for (int mi = 0; mi < MI; mi++) {
        #pragma unroll
        for (int ni = 0; ni < NI; ni++) {
            #pragma unroll
            for (int half = 0; half < 2; half++) {
                int m = m0 + wm + mi * 16 + g + half * 8;
                float v0 = acc[mi][ni][half * 2 + 0];
                float v1 = acc[mi][ni][half * 2 + 1];
                int n = n0 + wn + ni * 8 + tg * 2;
                if (EPI == 2) {
                    float2 w;
                    w.x = v0 + bias[n    ] + res[(size_t)m * N + n    ];
                    w.y = v1 + bias[n + 1] + res[(size_t)m * N + n + 1];
                    *(float2*)&C[(size_t)m * N + n] = w;
                } else if (EPI == 3) {
                    float t0 = v0 + bias[n], t1 = v1 + bias[n + 1];
                    t0 = 0.5f * t0 * (1.f + erff(t0 * 0.70710678118654752f));
                    t1 = 0.5f * t1 * (1.f + erff(t1 * 0.70710678118654752f));
                    ((uint32_t*)C)[((size_t)m * N + n) >> 1] = packbf(t0, t1);
                } else if (EPI == 5) {
                    #pragma unroll
                    for (int e = 0; e < 2; e++) {
                        float v = e ? v1 : v0;
                        int nn = n + e;
                        int which = nn >> 10;
                        int r = nn & 1023;
                        int hh = r >> 6, hd = r & 63;
                        int bb = m >> 10, t = m & 1023;
                        int bh = bb * Hh + hh;
                        if (which == 0)
                            g_qb[((size_t)bh * SEQm + t) * HDm + hd] =
                                __float2bfloat16_rn((v + bias[r]) * 0.125f);
                        else if (which == 1)
                            g_kb[((size_t)bh * SEQm + t) * HDm + hd] =
                                __float2bfloat16_rn(v);
                        else
                            g_vtb[((size_t)bh * HDm + hd) * SEQm + t] =
                                __float2bfloat16_rn(v + res[r]);
                    }
                }
            }
        }
    }
}

// ---------------------------------------------------------------------------
// Fused attention (no-max softmax) — unchanged from R15.
// ---------------------------------------------------------------------------
__global__ __launch_bounds__(256, 2)
void flash(const __nv_bfloat16* __restrict__ Q, const __nv_bfloat16* __restrict__ K,
           const __nv_bfloat16* __restrict__ Vt, __nv_bfloat16* __restrict__ O)
{
    __shared__ alignas(1024) uint32_t Qs[4096];
    __shared__ alignas(1024) uint32_t Ks[2][2048];
    __shared__ alignas(1024) uint32_t Vs[2][2048];

    int tid = threadIdx.x, lane = tid & 31, warp = tid >> 5;
    int g = lane >> 2, tg = lane & 3;
    int lr = lane & 15, lh = lane >> 4;
    int wm = warp * 16;
    int q0 = blockIdx.x * 128;
    long z = blockIdx.y;
    const __nv_bfloat16* Qb = Q + (z * SEQm + q0) * HDm;
    const __nv_bfloat16* Kb = K + z * (long)SEQm * HDm;
    const __nv_bfloat16* Vb = Vt + z * (long)SEQm * HDm;

    uint32_t sQ = (uint32_t)__cvta_generic_to_shared(&Qs[0]);
    uint32_t sK = (uint32_t)__cvta_generic_to_shared(&Ks[0][0]);
    uint32_t sV = (uint32_t)__cvta_generic_to_shared(&Vs[0][0]);

    #pragma unroll
    for (int i = tid; i < 1024; i += 256) {
        int seg = i >> 9, r = (i >> 2) & 127, c = i & 3;
        cp16(sQ + (uint32_t)((seg * 2048 + r * 16 + ((c ^ ((r >> 1) & 3)) << 2)) * 4),
             Qb + r * HDm + seg * 32 + c * 8);
    }
    asm volatile("cp.async.commit_group;");

    auto stageKV = [&](int st, int t0) {
        #pragma unroll
        for (int i = tid; i < 512; i += 256) {
            int seg = i >> 8, r = (i >> 2) & 63, c = i & 3;
            uint32_t off = (uint32_t)((st * 2048 + seg * 1024 + r * 16 +
                                       ((c ^ ((r >> 1) & 3)) << 2)) * 4);
            cp16(sK + off, Kb + (size_t)(t0 + r) * HDm + seg * 32 + c * 8);
        }
        #pragma unroll
        for (int i = tid; i < 512; i += 256) {
            int seg = i >> 8, r = (i >> 2) & 63, c = i & 3;
            uint32_t off = (uint32_t)((st * 2048 + seg * 1024 + r * 16 +
                                       ((c ^ ((r >> 1) & 3)) << 2)) * 4);
            cp16(sV + off, Vb + (size_t)r * SEQm + t0 + seg * 32 + c * 8);
        }
        asm volatile("cp.async.commit_group;");
    };

    stageKV(0, 0);
    asm volatile("cp.async.wait_group 0;");
    __syncthreads();

    uint32_t aq[4][4];
    {
        int rq = wm + lr;
        int swq = (rq >> 1) & 3;
        #pragma unroll
        for (int ch = 0; ch < 4; ch++) {
            int seg = ch >> 1, c16 = (ch & 1) * 2 + lh;
            ldsm4(aq[ch], sQ + (uint32_t)((seg * 2048 + rq * 16 +
                                           ((c16 ^ swq) << 2)) * 4));
        }
    }

    float accO[8][4] = {};
    float rs0 = 0.f, rs1 = 0.f;

    for (int jt = 0; jt < 16; jt++) {
        if (jt + 1 < 16) stageKV((jt + 1) & 1, (jt + 1) * 64);
        else             asm volatile("cp.async.commit_group;");
        asm volatile("cp.async.wait_group 1;");
        __syncthreads();

        uint32_t bK = sK + (uint32_t)((jt & 1) * 2048 * 4);
        uint32_t bV = sV + (uint32_t)((jt & 1) * 2048 * 4);

        float accS[8][4] = {};
        #pragma unroll
        for (int ch = 0; ch < 4; ch++) {
            int seg = ch >> 1, c16 = (ch & 1) * 2 + lh;
            uint32_t bfv[8][2];
            #pragma unroll
            for (int p = 0; p < 4; p++) {
                int rb = p * 16 + lr;
                uint32_t r4[4];
                ldsm4(r4, bK + (uint32_t)((seg * 1024 + rb * 16 +
                                           ((c16 ^ ((rb >> 1) & 3)) << 2)) * 4));
                bfv[2 * p    ][0] = r4[0];
                bfv[2 * p + 1][0] = r4[1];
                bfv[2 * p    ][1] = r4[2];
                bfv[2 * p + 1][1] = r4[3];
            }
            #pragma unroll
            for (int ni = 0; ni < 8; ni++)
                mma_bf16(accS[ni], aq[ch], bfv[ni]);
        }

        uint32_t ap[4][4];
        #pragma unroll
        for (int t = 0; t < 4; t++) {
            ap[t][0] = packbf(__expf(accS[2*t    ][0]), __expf(accS[2*t    ][1]));
            ap[t][1] = packbf(__expf(accS[2*t    ][2]), __expf(accS[2*t    ][3]));
            ap[t][2] = packbf(__expf(accS[2*t + 1][0]), __expf(accS[2*t + 1][1]));
            ap[t][3] = packbf(__expf(accS[2*t + 1][2]), __expf(accS[2*t + 1][3]));
            float2 f0 = __bfloat1622float2(*(__nv_bfloat162*)&ap[t][0]);
            float2 f2 = __bfloat1622float2(*(__nv_bfloat162*)&ap[t][2]);
            rs0 += (f0.x + f0.y) + (f2.x + f2.y);
            float2 f1 = __bfloat1622float2(*(__nv_bfloat162*)&ap[t][1]);
            float2 f3 = __bfloat1622float2(*(__nv_bfloat162*)&ap[t][3]);
            rs1 += (f1.x + f1.y) + (f3.x + f3.y);
        }

        #pragma unroll
        for (int ch = 0; ch < 4; ch++) {
            int seg = ch >> 1, c16 = (ch & 1) * 2 + lh;
            uint32_t bfv[8][2];
            #pragma unroll
            for (int p = 0; p < 4; p++) {
                int rb = p * 16 + lr;
                uint32_t r4[4];
                ldsm4(r4, bV + (uint32_t)((seg * 1024 + rb * 16 +
                                           ((c16 ^ ((rb >> 1) & 3)) << 2)) * 4));
                bfv[2 * p    ][0] = r4[0];
                bfv[2 * p + 1][0] = r4[1];
                bfv[2 * p    ][1] = r4[2];
                bfv[2 * p + 1][1] = r4[3];
            }
            #pragma unroll
            for (int ni = 0; ni < 8; ni++)
                mma_bf16(accO[ni], ap[ch], bfv[ni]);
        }
        __syncthreads();
    }

    rs0 += __shfl_xor_sync(0xffffffffu, rs0, 1);
    rs0 += __shfl_xor_sync(0xffffffffu, rs0, 2);
    rs1 += __shfl_xor_sync(0xffffffffu, rs1, 1);
    rs1 += __shfl_xor_sync(0xffffffffu, rs1, 2);
    float inv0 = 1.f / rs0, inv1 = 1.f / rs1;

    int bb = (int)(z >> 4), hh = (int)(z & 15);
    uint32_t* O32 = (uint32_t*)O;
    size_t base0 = ((size_t)bb * SEQm + q0 + wm + g) * Dm + hh * HDm;
    size_t base1 = base0 + (size_t)8 * Dm;
    #pragma unroll
    for (int ni = 0; ni < 8; ni++) {
        int c = ni * 8 + tg * 2;
        O32[(base0 + c) >> 1] = packbf(accO[ni][0] * inv0, accO[ni][1] * inv0);
        O32[(base1 + c) >> 1] = packbf(accO[ni][2] * inv1, accO[ni][3] * inv1);
    }
}

// ---------------------------------------------------------------------------
extern "C" void kernel_launch(void* const* d_in, const int* in_sizes, int n_in,
                              void* d_out, int out_size)
{
    const float* x      = (const float*)d_in[0];
    const float* ln1_g  = (const float*)d_in[1];
    const float* ln1_b  = (const float*)d_in[2];
    const float* ln2_g  = (const float*)d_in[3];
    const float* ln2_b  = (const float*)d_in[4];
    const float* qkv_w  = (const float*)d_in[5];
    const float* q_bias = (const float*)d_in[6];
    const float* v_bias = (const float*)d_in[7];
    const float* proj_w = (const float*)d_in[8];
    const float* proj_b = (const float*)d_in[9];
    const float* fc1_w  = (const float*)d_in[10];
    const float* fc1_b  = (const float*)d_in[11];
    const float* fc2_w  = (const float*)d_in[12];
    const float* fc2_b  = (const float*)d_in[13];
    float* out = (float*)d_out;

    __nv_bfloat16 *hb, *qb, *kb, *vtb, *ob, *gb, *wq, *wp, *w1, *w2;
    float *x1;
    cudaGetSymbolAddress((void**)&hb,  g_hb);
    cudaGetSymbolAddress((void**)&qb,  g_qb);
    cudaGetSymbolAddress((void**)&kb,  g_kb);
    cudaGetSymbolAddress((void**)&vtb, g_vtb);
    cudaGetSymbolAddress((void**)&ob,  g_ob);
    cudaGetSymbolAddress((void**)&gb,  g_gb);
    cudaGetSymbolAddress((void**)&x1,  g_x1);
    cudaGetSymbolAddress((void**)&wq,  w_qkv);
    cudaGetSymbolAddress((void**)&wp,  w_proj);
    cudaGetSymbolAddress((void**)&w1,  w_fc1);
    cudaGetSymbolAddress((void**)&w2,  w_fc2);

    // 0. weight conversion to bf16 (single launch)
    {
        int total = N_QKV + N_PRJ + N_FC1 + N_FC2;
        cvt4_kernel<<<(total + 255) / 256, 256>>>(qkv_w, proj_w, fc1_w, fc2_w,
                                                  wq, wp, w1, w2);
    }

    // 1. LN1 -> bf16
    ln_kernel<<<TOKm, 256>>>(x, ln1_g, ln1_b, hb);

    // 2. QKV = h @ qkv_w^T, fused scatter (q scaled+biased, k, v^T biased)
    tgemm<5><<<dim3(3072/128, TOKm/128), 256>>>(
        hb, wq, nullptr, TOKm, 3*Dm, Dm, q_bias, v_bias);

    // 3. fused attention: o = softmax(q k^T) v -> bf16 [b,t,(h,hd)]
    flash<<<dim3(SEQm/128, BHm), 256>>>(qb, kb, vtb, ob);

    // 4. x1 = x + o @ proj_w^T + proj_b  (fp32)
    tgemm<2><<<dim3(Dm/128, TOKm/128), 256>>>(
        ob, wp, x1, TOKm, Dm, Dm, proj_b, x);

    // 5. LN2 -> bf16
    ln_kernel<<<TOKm, 256>>>(x1, ln2_g, ln2_b, hb);

    // 6. g = gelu(h @ fc1_w^T + fc1_b) -> bf16
    tgemm<3><<<dim3(FFm/128, TOKm/128), 256>>>(
        hb, w1, (float*)gb, TOKm, FFm, Dm, fc1_b, nullptr);

    // 7. out = x1 + g @ fc2_w^T + fc2_b  (fp32)
    tgemm<2><<<dim3(Dm/128, TOKm/128), 256>>>(
        gb, w2, out, TOKm, Dm, FFm, fc2_b, x1);
}